// round 14
// baseline (speedup 1.0000x reference)
#include <cuda_runtime.h>
#include <cuda_fp16.h>
#include <cstdint>
#include <math.h>

// ----------------------------------------------------------------------------
// B=16384, D=512, H=256, R=95, KJ=64. TB=64 rows/CTA, 256 threads (8 warps,
// 2m x 4n warp grid, warp tile 32x64), 2 CTAs/SM, grid=256 (single wave).
// mma.sync m16n8k16 fp16, packed-K scheme: A exact fp16 hi/lo, B single fp16.
// R14: branch-free A&S erf GELU (abs err 1.5e-7) replaces erff.
// ----------------------------------------------------------------------------

#define TB 64
#define NT 256

// smem byte offsets
#define OFF_A1   0        // GEMM1 A staging [64][272] (hi/lo interleaved k16 slices)
#define OFF_B1   17408    // GEMM1 B staging [256][144] single fp16, ends 54272
#define OFF_X    0        // x slabs: [4 slab][64][272] = 69632 (overlays staging)
#define OFF_MB   69632    // mbuf [2][64][65] f32 = 33280, ends 102912
#define OFF_ST   102912   // stats [64][8] f32 = 2048
#define SMEM_BYTES 104960
// P slab (post-GEMM2): [64][272] @ OFF_X

static __device__ __forceinline__ uint32_t smem_u32(const void* p) {
    uint32_t a;
    asm("{ .reg .u64 t; cvta.to.shared.u64 t, %1; cvt.u32.u64 %0, t; }" : "=r"(a) : "l"(p));
    return a;
}

static __device__ __forceinline__ void ldsm4(uint32_t* r, uint32_t addr) {
    asm volatile("ldmatrix.sync.aligned.m8n8.x4.shared.b16 {%0,%1,%2,%3}, [%4];"
                 : "=r"(r[0]), "=r"(r[1]), "=r"(r[2]), "=r"(r[3]) : "r"(addr));
}

static __device__ __forceinline__ void mma16816(float* c, const uint32_t* a,
                                                uint32_t b0, uint32_t b1) {
    asm volatile(
        "mma.sync.aligned.m16n8k16.row.col.f32.f16.f16.f32 "
        "{%0,%1,%2,%3}, {%4,%5,%6,%7}, {%8,%9}, {%0,%1,%2,%3};"
        : "+f"(c[0]), "+f"(c[1]), "+f"(c[2]), "+f"(c[3])
        : "r"(a[0]), "r"(a[1]), "r"(a[2]), "r"(a[3]), "r"(b0), "r"(b1));
}

static __device__ __forceinline__ void cp16(uint32_t dst, const void* src) {
    asm volatile("cp.async.cg.shared.global [%0], [%1], 16;" :: "r"(dst), "l"(src));
}

// single fp16x2 round (elem0 in low half)
static __device__ __forceinline__ uint32_t pack_h2(float a0, float a1) {
    uint32_t r;
    asm("cvt.rn.f16x2.f32 %0, %1, %2;" : "=r"(r) : "f"(a1), "f"(a0));
    return r;
}

// exact fp16 hi/lo split of a float pair, packed (elem0 in low half)
static __device__ __forceinline__ void split2h(float a0, float a1, uint32_t& hi, uint32_t& lo) {
    asm("cvt.rn.f16x2.f32 %0, %1, %2;" : "=r"(hi) : "f"(a1), "f"(a0));
    __half2 h = *reinterpret_cast<__half2*>(&hi);
    float f0 = __half2float(__low2half(h));
    float f1 = __half2float(__high2half(h));
    asm("cvt.rn.f16x2.f32 %0, %1, %2;" : "=r"(lo) : "f"(a1 - f1), "f"(a0 - f0));
}

// branch-free exact-erf GELU via Abramowitz-Stegun 7.1.26 (abs err 1.5e-7)
static __device__ __forceinline__ float gelu_fast(float y) {
    float z  = y * 0.70710678118654752f;
    float az = fabsf(z);
    float t  = __fdividef(1.f, fmaf(0.3275911f, az, 1.f));
    float e  = __expf(-az * az);
    float poly = 1.061405429f;
    poly = fmaf(poly, t, -1.453152027f);
    poly = fmaf(poly, t, 1.421413741f);
    poly = fmaf(poly, t, -0.284496736f);
    poly = fmaf(poly, t, 0.254829592f);
    poly *= t;
    float erfv = fmaf(-poly, e, 1.f);          // erf(|z|)
    erfv = copysignf(erfv, z);
    return 0.5f * y * (1.f + erfv);
}

// weight scratch (all single fp16 packed pairs)
__device__ __align__(16) uint32_t g_w1t[2][256 * 256];   // W1^T [n=256][kp=256]
__device__ __align__(16) uint32_t g_w2f[2][64 * 128];    // W2^T frag-ordered
__device__ __align__(16) uint32_t g_ttf[96 * 32];        // T^T/8 frag-ordered

__global__ void prep_kernel(const float* __restrict__ Wp1, const float* __restrict__ Wv1,
                            const float* __restrict__ Wp2, const float* __restrict__ Wv2,
                            const float* __restrict__ Tm) {
    int idx = blockIdx.x * blockDim.x + threadIdx.x;
    if (idx < 65536) {
        int n = idx >> 8, kp = idx & 255;
#pragma unroll
        for (int p = 0; p < 2; ++p) {
            const float* W1 = p ? Wv1 : Wp1;
            g_w1t[p][n * 256 + kp] =
                pack_h2(W1[(2 * kp) * 256 + n], W1[(2 * kp + 1) * 256 + n]);
        }
    } else if (idx < 65536 + 8192) {
        int j = idx - 65536;
        int n = j >> 7, kp2 = j & 127;
        int s = kp2 >> 3, r3 = kp2 & 7, t2 = r3 >> 1, e = r3 & 1;
        int kp = s * 8 + t2 + 4 * e;
#pragma unroll
        for (int p = 0; p < 2; ++p) {
            const float* W2 = p ? Wv2 : Wp2;
            g_w2f[p][n * 128 + kp2] =
                pack_h2(W2[(2 * kp) * 64 + n], W2[(2 * kp + 1) * 64 + n]);
        }
    } else if (idx < 65536 + 8192 + 3072) {
        int j = idx - 65536 - 8192;
        int nrow = j >> 5, kp2 = j & 31;
        int s = kp2 >> 3, r3 = kp2 & 7, t2 = r3 >> 1, e = r3 & 1;
        int kp = s * 8 + t2 + 4 * e;
        float a0 = 0.f, a1 = 0.f;
        if (nrow < 95) {
            a0 = Tm[nrow * 64 + 2 * kp] * 0.125f;
            a1 = Tm[nrow * 64 + 2 * kp + 1] * 0.125f;
        }
        g_ttf[nrow * 32 + kp2] = pack_h2(a0, a1);
    }
}

__global__ __launch_bounds__(NT, 2)
void clifford_mma_kernel(
    const float* __restrict__ h_perp, const float* __restrict__ h_vuln,
    const float* __restrict__ bp1, const float* __restrict__ lgp,
    const float* __restrict__ lbp, const float* __restrict__ bp2,
    const float* __restrict__ bv1, const float* __restrict__ lgv,
    const float* __restrict__ lbv, const float* __restrict__ bv2,
    const float* __restrict__ gw,
    float* __restrict__ out)
{
    extern __shared__ char smem[];
    const uint32_t sb = smem_u32(smem);
    const int tid = threadIdx.x;
    const int lane = tid & 31;
    const int wid = tid >> 5;     // 0..7
    const int wm = wid & 1;       // GEMM1 m-block: rows wm*32..+32
    const int wn = wid >> 1;      // GEMM1 n-block: cols wn*64..+64
    const int wm2 = wid & 3;      // GEMM2/T-GEMM m-block: rows wm2*16..+16
    const int wn2 = wid >> 2;     // GEMM2 n-block: cols wn2*32 / T: wn2*48
    const int g = lane >> 2, t = lane & 3;
    const int g8 = lane & 7, m4 = lane >> 3;
    const int r0 = blockIdx.x * TB;

    float* mbuf  = (float*)(smem + OFF_MB);
    float* stats = (float*)(smem + OFF_ST);

    // common fragment addressing pieces
    const int arow1 = g8 + ((m4 & 1) << 3);
    const uint32_t acolb = (uint32_t)((m4 & 2) << 3);

    for (int p = 0; p < 2; ++p) {
        const float* hsrc = p ? h_vuln : h_perp;
        const uint32_t* w1t = g_w1t[p];
        const uint32_t* w2f = g_w2f[p];
        const float* b1 = p ? bv1 : bp1;
        const float* lg = p ? lgv : lgp;
        const float* lb = p ? lbv : lbp;
        const float* b2 = p ? bv2 : bp2;

        // ===== GEMM1: acc[64,256] = h @ W1, warp tile 32x64 =====
        float acc[2][8][4];
#pragma unroll
        for (int mi = 0; mi < 2; ++mi)
#pragma unroll
            for (int j = 0; j < 8; ++j)
#pragma unroll
                for (int q = 0; q < 4; ++q) acc[mi][j][q] = 0.f;

        for (int kk = 0; kk < 512; kk += 64) {
            __syncthreads();
            // B staging via cp.async: 256 rows x 32 u32 (single fp16), stride 144
#pragma unroll
            for (int z = 0; z < 8; ++z) {
                int i = tid + z * NT;
                int row = i >> 3, q = i & 7;
                cp16(sb + OFF_B1 + (uint32_t)(row * 144 + q * 16),
                     w1t + row * 256 + (kk >> 1) + q * 4);
            }
            asm volatile("cp.async.commit_group;");
            // A staging: 64x64 fp32 -> fp16 hi/lo interleaved slices, stride 272
#pragma unroll
            for (int z = 0; z < 4; ++z) {
                int i = tid + z * NT;
                int row = i >> 4, gq = i & 15;
                float4 v = *(const float4*)(hsrc + (size_t)(r0 + row) * 512 + kk + gq * 4);
                uint32_t h0, l0, h1, l1;
                split2h(v.x, v.y, h0, l0);
                split2h(v.z, v.w, h1, l1);
                int s_loc = gq >> 2, w = gq & 3;
                char* base = smem + OFF_A1 + row * 272 + s_loc * 64 + w * 8;
                *(uint2*)(base)      = make_uint2(h0, h1);
                *(uint2*)(base + 32) = make_uint2(l0, l1);
            }
            asm volatile("cp.async.wait_group 0;");
            __syncthreads();

            for (int s = 0; s < 4; ++s) {
                uint32_t ah[2][4], al[2][4];
#pragma unroll
                for (int mi = 0; mi < 2; ++mi) {
                    uint32_t ao = sb + OFF_A1 + (uint32_t)((wm * 32 + mi * 16 + arow1) * 272
                                 + s * 64) + acolb;
                    ldsm4(ah[mi], ao);
                    ldsm4(al[mi], ao + 32);
                }
                uint32_t bfr[4][4];
#pragma unroll
                for (int jp = 0; jp < 4; ++jp) {
                    int brow = wn * 64 + jp * 16 + g8 + ((m4 & 2) << 2);
                    uint32_t bo = sb + OFF_B1 + (uint32_t)(brow * 144 + s * 32)
                                 + ((uint32_t)(m4 & 1) << 4);
                    ldsm4(bfr[jp], bo);
                }
#pragma unroll
                for (int jp = 0; jp < 4; ++jp)
#pragma unroll
                    for (int hh = 0; hh < 2; ++hh)
#pragma unroll
                        for (int mi = 0; mi < 2; ++mi)
                            mma16816(acc[mi][jp * 2 + hh], ah[mi],
                                     bfr[jp][2 * hh], bfr[jp][2 * hh + 1]);
#pragma unroll
                for (int jp = 0; jp < 4; ++jp)
#pragma unroll
                    for (int hh = 0; hh < 2; ++hh)
#pragma unroll
                        for (int mi = 0; mi < 2; ++mi)
                            mma16816(acc[mi][jp * 2 + hh], al[mi],
                                     bfr[jp][2 * hh], bfr[jp][2 * hh + 1]);
            }
        }

        // ===== LayerNorm stats (bias folded into acc in place) =====
        float s1[2][2] = {{0.f, 0.f}, {0.f, 0.f}};
        float s2a[2][2] = {{0.f, 0.f}, {0.f, 0.f}};
#pragma unroll
        for (int j = 0; j < 8; ++j) {
            float2 b1v = *(const float2*)(b1 + wn * 64 + 8 * j + 2 * t);
#pragma unroll
            for (int mi = 0; mi < 2; ++mi) {
                float v0 = acc[mi][j][0] + b1v.x, v1 = acc[mi][j][1] + b1v.y;
                float v2 = acc[mi][j][2] + b1v.x, v3 = acc[mi][j][3] + b1v.y;
                acc[mi][j][0] = v0; acc[mi][j][1] = v1;
                acc[mi][j][2] = v2; acc[mi][j][3] = v3;
                s1[mi][0] += v0 + v1;  s2a[mi][0] += v0 * v0 + v1 * v1;
                s1[mi][1] += v2 + v3;  s2a[mi][1] += v2 * v2 + v3 * v3;
            }
        }
#pragma unroll
        for (int mi = 0; mi < 2; ++mi)
#pragma unroll
            for (int rp = 0; rp < 2; ++rp) {
                s1[mi][rp]  += __shfl_xor_sync(0xFFFFFFFFu, s1[mi][rp], 1);
                s1[mi][rp]  += __shfl_xor_sync(0xFFFFFFFFu, s1[mi][rp], 2);
                s2a[mi][rp] += __shfl_xor_sync(0xFFFFFFFFu, s2a[mi][rp], 1);
                s2a[mi][rp] += __shfl_xor_sync(0xFFFFFFFFu, s2a[mi][rp], 2);
            }
        if (t == 0) {
#pragma unroll
            for (int mi = 0; mi < 2; ++mi)
#pragma unroll
                for (int rp = 0; rp < 2; ++rp) {
                    int row = wm * 32 + mi * 16 + g + 8 * rp;
                    stats[row * 8 + wn * 2]     = s1[mi][rp];
                    stats[row * 8 + wn * 2 + 1] = s2a[mi][rp];
                }
        }
        __syncthreads();
        float mu[2][2], rs[2][2];
#pragma unroll
        for (int mi = 0; mi < 2; ++mi)
#pragma unroll
            for (int rp = 0; rp < 2; ++rp) {
                int row = wm * 32 + mi * 16 + g + 8 * rp;
                float S  = stats[row * 8] + stats[row * 8 + 2] + stats[row * 8 + 4] + stats[row * 8 + 6];
                float S2 = stats[row * 8 + 1] + stats[row * 8 + 3] + stats[row * 8 + 5] + stats[row * 8 + 7];
                float m = S * (1.f / 256.f);
                float var = S2 * (1.f / 256.f) - m * m;
                mu[mi][rp] = m;
                rs[mi][rp] = rsqrtf(var + 1e-5f);
            }
        __syncthreads();   // staging reads done before X overwrites region

        // ===== GELU + pack -> x slabs (fp16 hi/lo slices, stride 272) =====
        const int xbase = OFF_X + wn * 17408;
#pragma unroll
        for (int j = 0; j < 8; ++j) {
            int cl = 8 * j + 2 * t;
            int cg = wn * 64 + cl;
            float2 lgv = *(const float2*)(lg + cg);
            float2 lbv = *(const float2*)(lb + cg);
            int s2 = cl >> 4, wofs = (cl & 15) * 2;
#pragma unroll
            for (int mi = 0; mi < 2; ++mi) {
                int rowt = wm * 32 + mi * 16 + g;
                {
                    float y0 = (acc[mi][j][0] - mu[mi][0]) * rs[mi][0] * lgv.x + lbv.x;
                    float y1 = (acc[mi][j][1] - mu[mi][0]) * rs[mi][0] * lgv.y + lbv.y;
                    float g0 = gelu_fast(y0);
                    float g1 = gelu_fast(y1);
                    uint32_t hh, ll;
                    split2h(g0, g1, hh, ll);
                    char* base = smem + xbase + rowt * 272 + s2 * 64 + wofs;
                    *(uint32_t*)(base)      = hh;
                    *(uint32_t*)(base + 32) = ll;
                }
                {
                    float y0 = (acc[mi][j][2] - mu[mi][1]) * rs[mi][1] * lgv.x + lbv.x;
                    float y1 = (acc[mi][j][3] - mu[mi][1]) * rs[mi][1] * lgv.y + lbv.y;
                    float g0 = gelu_fast(y0);
                    float g1 = gelu_fast(y1);
                    uint32_t hh, ll;
                    split2h(g0, g1, hh, ll);
                    char* base = smem + xbase + (rowt + 8) * 272 + s2 * 64 + wofs;
                    *(uint32_t*)(base)      = hh;
                    *(uint32_t*)(base + 32) = ll;
                }
            }
        }
        __syncthreads();

        // ===== GEMM2: m[64,64] = x @ W2, warp tile 16x32, prefetch-pipelined =====
        float a2[4][4];
#pragma unroll
        for (int j = 0; j < 4; ++j)
#pragma unroll
            for (int q = 0; q < 4; ++q) a2[j][q] = 0.f;

        {
            const int arow2 = wm2 * 16 + arow1;
            uint32_t AH[2][4], AL[2][4];
            uint2 BF[2][4];
            {
                uint32_t ao = sb + OFF_X + (uint32_t)(arow2 * 272) + acolb;
                ldsm4(AH[0], ao);
                ldsm4(AL[0], ao + 32);
#pragma unroll
                for (int j2 = 0; j2 < 4; ++j2)
                    BF[0][j2] = *(const uint2*)(w2f + (wn2 * 32 + j2 * 8 + g) * 128 + 2 * t);
            }
#pragma unroll
            for (int s = 0; s < 16; ++s) {
                int cur = s & 1, nxt = cur ^ 1;
                if (s < 15) {
                    int sn = s + 1, slab = sn >> 2, sl = sn & 3;
                    uint32_t ao = sb + OFF_X + (uint32_t)(slab * 17408 + arow2 * 272
                                 + sl * 64) + acolb;
                    ldsm4(AH[nxt], ao);
                    ldsm4(AL[nxt], ao + 32);
#pragma unroll
                    for (int j2 = 0; j2 < 4; ++j2)
                        BF[nxt][j2] = *(const uint2*)(w2f + (wn2 * 32 + j2 * 8 + g) * 128
                                      + sn * 8 + 2 * t);
                }
#pragma unroll
                for (int j2 = 0; j2 < 4; ++j2)
                    mma16816(a2[j2], AH[cur], BF[cur][j2].x, BF[cur][j2].y);
#pragma unroll
                for (int j2 = 0; j2 < 4; ++j2)
                    mma16816(a2[j2], AL[cur], BF[cur][j2].x, BF[cur][j2].y);
            }
        }
        float* mb = mbuf + p * 4160;
        {
            int rowt = wm2 * 16 + g;
#pragma unroll
            for (int j2 = 0; j2 < 4; ++j2) {
                int c0 = wn2 * 32 + j2 * 8 + 2 * t;
                float2 b2v = *(const float2*)(b2 + c0);
                mb[rowt * 65 + c0]           = a2[j2][0] + b2v.x;
                mb[rowt * 65 + c0 + 1]       = a2[j2][1] + b2v.y;
                mb[(rowt + 8) * 65 + c0]     = a2[j2][2] + b2v.x;
                mb[(rowt + 8) * 65 + c0 + 1] = a2[j2][3] + b2v.y;
            }
        }
        __syncthreads();
    }

    // ===== Cayley contraction with gw -> P slab (fp16 hi/lo, stride 272) =====
    float gwr[8];
#pragma unroll
    for (int n = 0; n < 8; ++n) gwr[n] = gw[n];
    const int MASKc[8] = {0, 1, 2, 4, 3, 5, 6, 7};
    {
        int row = tid & 63;
        int kb2 = (tid >> 6) * 2;
        const float* mp = mbuf + row * 65;
        const float* mv = mbuf + 4160 + row * 65;
#pragma unroll
        for (int kk2 = 0; kk2 < 2; ++kk2) {
            int k = kb2 + kk2;
            float mpv[8], mvv[8];
#pragma unroll
            for (int i = 0; i < 8; ++i) { mpv[i] = mp[k * 8 + i]; mvv[i] = mv[k * 8 + i]; }
            float Q[8];
#pragma unroll
            for (int m = 0; m < 8; ++m) {
                float q = 0.f;
#pragma unroll
                for (int j = 0; j < 8; ++j) {
                    int am = MASKc[m], bm = MASKc[j];
                    int sw = __popc((am >> 1) & bm) + __popc((am >> 2) & bm);
                    float sg = (sw & 1) ? -1.f : 1.f;
                    q += sg * gwr[MASKc[am ^ bm]] * mvv[j];
                }
                Q[m] = q;
            }
            float pvv[8];
#pragma unroll
            for (int j = 0; j < 8; ++j) {
                float pv = 0.f;
#pragma unroll
                for (int i = 0; i < 8; ++i) {
                    int am = MASKc[i], bm = MASKc[j];
                    int sw = __popc((am >> 1) & bm) + __popc((am >> 2) & bm);
                    float sg = (sw & 1) ? -1.f : 1.f;
                    pv += sg * mpv[i] * Q[MASKc[am ^ bm]];
                }
                pvv[j] = pv;
            }
#pragma unroll
            for (int j = 0; j < 8; j += 2) {
                uint32_t hh, ll;
                split2h(pvv[j], pvv[j + 1], hh, ll);
                char* base = smem + OFF_X + row * 272 + (k >> 1) * 64 + (k & 1) * 16 + j * 2;
                *(uint32_t*)(base)      = hh;
                *(uint32_t*)(base + 32) = ll;
            }
        }
    }
    __syncthreads();

    // ===== T-GEMM: out[64,95] = P[64,64] @ Tt[64,96], prefetch-pipelined =====
    {
        float a3[6][4];
#pragma unroll
        for (int j = 0; j < 6; ++j)
#pragma unroll
            for (int q = 0; q < 4; ++q) a3[j][q] = 0.f;

        const int arow2 = wm2 * 16 + arow1;
        uint32_t PH[2][4], PL[2][4];
        uint2 TF[2][6];
        {
            uint32_t ao = sb + OFF_X + (uint32_t)(arow2 * 272) + acolb;
            ldsm4(PH[0], ao);
            ldsm4(PL[0], ao + 32);
#pragma unroll
            for (int j2 = 0; j2 < 6; ++j2)
                TF[0][j2] = *(const uint2*)(g_ttf + (wn2 * 48 + j2 * 8 + g) * 32 + 2 * t);
        }
#pragma unroll
        for (int s = 0; s < 4; ++s) {
            int cur = s & 1, nxt = cur ^ 1;
            if (s < 3) {
                int sn = s + 1;
                uint32_t ao = sb + OFF_X + (uint32_t)(arow2 * 272 + sn * 64) + acolb;
                ldsm4(PH[nxt], ao);
                ldsm4(PL[nxt], ao + 32);
#pragma unroll
                for (int j2 = 0; j2 < 6; ++j2)
                    TF[nxt][j2] = *(const uint2*)(g_ttf + (wn2 * 48 + j2 * 8 + g) * 32
                                  + sn * 8 + 2 * t);
            }
#pragma unroll
            for (int j2 = 0; j2 < 6; ++j2)
                mma16816(a3[j2], PH[cur], TF[cur][j2].x, TF[cur][j2].y);
#pragma unroll
            for (int j2 = 0; j2 < 6; ++j2)
                mma16816(a3[j2], PL[cur], TF[cur][j2].x, TF[cur][j2].y);
        }
        int rowt = r0 + wm2 * 16 + g;
#pragma unroll
        for (int j2 = 0; j2 < 6; ++j2) {
            int col = wn2 * 48 + j2 * 8 + 2 * t;
            if (col < 95) {
                out[(size_t)rowt * 95 + col]       = a3[j2][0];
                out[(size_t)(rowt + 8) * 95 + col] = a3[j2][2];
            }
            if (col + 1 < 95) {
                out[(size_t)rowt * 95 + col + 1]       = a3[j2][1];
                out[(size_t)(rowt + 8) * 95 + col + 1] = a3[j2][3];
            }
        }
    }
}

extern "C" void kernel_launch(void* const* d_in, const int* in_sizes, int n_in,
                              void* d_out, int out_size) {
    const float* h_perp = (const float*)d_in[0];
    const float* h_vuln = (const float*)d_in[1];
    const float* Wp1 = (const float*)d_in[2];
    const float* bp1 = (const float*)d_in[3];
    const float* lgp = (const float*)d_in[4];
    const float* lbp = (const float*)d_in[5];
    const float* Wp2 = (const float*)d_in[6];
    const float* bp2 = (const float*)d_in[7];
    const float* Wv1 = (const float*)d_in[8];
    const float* bv1 = (const float*)d_in[9];
    const float* lgv = (const float*)d_in[10];
    const float* lbv = (const float*)d_in[11];
    const float* Wv2 = (const float*)d_in[12];
    const float* bv2 = (const float*)d_in[13];
    const float* Tm  = (const float*)d_in[14];
    const float* gw  = (const float*)d_in[15];
    float* out = (float*)d_out;

    int B = in_sizes[0] / 512;   // 16384
    int grid = B / TB;           // 256 (single wave at 2 CTAs/SM)

    prep_kernel<<<(65536 + 8192 + 3072 + 255) / 256, 256>>>(Wp1, Wv1, Wp2, Wv2, Tm);

    cudaFuncSetAttribute(clifford_mma_kernel,
                         cudaFuncAttributeMaxDynamicSharedMemorySize, SMEM_BYTES);
    clifford_mma_kernel<<<grid, NT, SMEM_BYTES>>>(
        h_perp, h_vuln, bp1, lgp, lbp, bp2, bv1, lgv, lbv, bv2, gw, out);
}